// round 1
// baseline (speedup 1.0000x reference)
#include <cuda_runtime.h>
#include <math.h>
#include <stdint.h>

#define LSEQ 1026
#define BB   2
#define BLT  (BB*LSEQ)   // 2052
#define DMO  256
#define EDI  512
#define ED2  1024
#define NS   16
#define RRW  16
#define DBCW 48
#define NBR  4
#define NCHK 18
#define CLEN 57          // 18*57 = 1026

// ------------------------- scratch (device globals; no allocs) -------------
__device__ float g_xz[(size_t)BLT*ED2];              // 8.4 MB
__device__ float g_xa[NBR][(size_t)BLT*EDI];         // 16.8 MB
__device__ float g_dbc[NBR][(size_t)BLT*DBCW];       // 1.6 MB
__device__ float g_delta[NBR][(size_t)BLT*EDI];      // 16.8 MB
__device__ float g_sum[(size_t)NBR*BB*NCHK*32*EDI];  // 9.4 MB
__device__ float g_h0[(size_t)NBR*BB*NCHK*NS*EDI];   // 4.7 MB
__device__ float g_g[NBR][(size_t)BLT*EDI];          // 16.8 MB
__device__ float g_y[(size_t)BLT*EDI];               // 4.2 MB
__device__ int   g_fast[NBR];

struct BranchPtrs { const float *cw,*cb,*xpw,*dtw,*dtb,*Al,*Dp; };
struct AllPtrs { BranchPtrs br[NBR]; };

// ------------------------- index maps ---------------------------------------
__device__ __forceinline__ int pi_map(int p) {
    if (p == 0 || p == LSEQ - 1) return p;
    int q = p - 1;
    int i = q >> 5, j = q & 31;
    return (j << 5) + i + 1;
}
__device__ __forceinline__ int in_row(int s, int p) {
    if (s == 0) return p;
    if (s == 1) return LSEQ - 1 - p;
    if (s == 2) return pi_map(p);
    return pi_map(LSEQ - 1 - p);
}

// ------------------------- generic SGEMM: C[m,n] = sum_k A[m,k]*B[n,k] ------
__global__ __launch_bounds__(256)
void sgemm_nt(const float* __restrict__ A, const float* __restrict__ Bm,
              float* __restrict__ C, int M, int N, int K) {
    __shared__ float As[16][64];
    __shared__ float Bs[16][64];
    int tid = threadIdx.x;
    int tx = tid & 15, ty = tid >> 4;
    int m0 = blockIdx.y * 64, n0 = blockIdx.x * 64;

    float acc[4][4];
#pragma unroll
    for (int i = 0; i < 4; i++)
#pragma unroll
        for (int j = 0; j < 4; j++) acc[i][j] = 0.f;

    int r = tid >> 2, kq = (tid & 3) * 4;
    for (int k0 = 0; k0 < K; k0 += 16) {
        float4 v = make_float4(0.f, 0.f, 0.f, 0.f);
        int m = m0 + r;
        if (m < M) v = *(const float4*)(A + (size_t)m * K + k0 + kq);
        As[kq + 0][r] = v.x; As[kq + 1][r] = v.y;
        As[kq + 2][r] = v.z; As[kq + 3][r] = v.w;
        float4 w = make_float4(0.f, 0.f, 0.f, 0.f);
        int n = n0 + r;
        if (n < N) w = *(const float4*)(Bm + (size_t)n * K + k0 + kq);
        Bs[kq + 0][r] = w.x; Bs[kq + 1][r] = w.y;
        Bs[kq + 2][r] = w.z; Bs[kq + 3][r] = w.w;
        __syncthreads();
#pragma unroll
        for (int k = 0; k < 16; k++) {
            float4 av = *(float4*)&As[k][ty * 4];
            float4 bv = *(float4*)&Bs[k][tx * 4];
            float a4[4] = {av.x, av.y, av.z, av.w};
            float b4[4] = {bv.x, bv.y, bv.z, bv.w};
#pragma unroll
            for (int i = 0; i < 4; i++)
#pragma unroll
                for (int j = 0; j < 4; j++)
                    acc[i][j] = fmaf(a4[i], b4[j], acc[i][j]);
        }
        __syncthreads();
    }
#pragma unroll
    for (int i = 0; i < 4; i++) {
        int m = m0 + ty * 4 + i;
        if (m >= M) continue;
#pragma unroll
        for (int j = 0; j < 4; j++) {
            int n = n0 + tx * 4 + j;
            if (n < N) C[(size_t)m * N + n] = acc[i][j];
        }
    }
}

// ------------------------- structure check for A = -(n+1) -------------------
__global__ void flag_kernel(AllPtrs P) {
    __shared__ int ok;
    int s = blockIdx.x;
    if (threadIdx.x == 0) ok = 1;
    __syncthreads();
    const float* Al = P.br[s].Al;
    int e = threadIdx.x;
    bool good = true;
#pragma unroll
    for (int n = 0; n < NS; n++) {
        float ref = logf((float)(n + 1));
        if (fabsf(Al[e * NS + n] - ref) > 1e-5f * fmaxf(1.f, fabsf(ref))) good = false;
    }
    if (!good) atomicAnd(&ok, 0);
    __syncthreads();
    if (threadIdx.x == 0) g_fast[s] = ok;
}

// ------------------------- depthwise conv (K=4 causal) + SiLU ---------------
__global__ void conv_silu(AllPtrs P) {
    int blk = blockIdx.x;
    int s = blk / BLT, bl = blk % BLT;
    int b = bl / LSEQ, l = bl % LSEQ;
    int e = threadIdx.x;
    const float* cw = P.br[s].cw;
    const float* cb = P.br[s].cb;
    float acc = cb[e];
#pragma unroll
    for (int k = 0; k < 4; k++) {
        int p = l - 3 + k;
        if (p >= 0) {
            int row = b * LSEQ + in_row(s, p);
            acc = fmaf(cw[e * 4 + k], g_xz[(size_t)row * ED2 + e], acc);
        }
    }
    float sg = 1.f / (1.f + __expf(-acc));
    g_xa[s][(size_t)bl * EDI + e] = acc * sg;
}

// ------------------------- delta = softplus(dbc[:16] @ dtw^T + dtb) ---------
__global__ void delta_kernel(AllPtrs P) {
    int blk = blockIdx.x;
    int s = blk / BLT, bl = blk % BLT;
    int e = threadIdx.x;
    __shared__ float f[RRW];
    if (threadIdx.x < RRW) f[threadIdx.x] = g_dbc[s][(size_t)bl * DBCW + threadIdx.x];
    __syncthreads();
    const float* dtw = P.br[s].dtw;
    float u = P.br[s].dtb[e];
#pragma unroll
    for (int r = 0; r < RRW; r++) u = fmaf(f[r], dtw[e * RRW + r], u);
    float d = fmaxf(u, 0.f) + log1pf(__expf(-fabsf(u)));
    g_delta[s][(size_t)bl * EDI + e] = d;
}

// ------------------------- scan phase 1: chunk summaries --------------------
__global__ __launch_bounds__(512)
void scan1(AllPtrs P) {
    int blk = blockIdx.x;
    int s = blk / (BB * NCHK);
    int rem = blk % (BB * NCHK);
    int b = rem / NCHK, c = rem % NCHK;
    int e = threadIdx.x;
    __shared__ float Bsm[CLEN * NS];
    for (int idx = threadIdx.x; idx < CLEN * NS; idx += blockDim.x) {
        int t = idx / NS, n = idx % NS;
        int bl = b * LSEQ + c * CLEN + t;
        Bsm[idx] = g_dbc[s][(size_t)bl * DBCW + RRW + n];
    }
    __syncthreads();
    int fast = g_fast[s];
    float A_[NS];
    if (!fast) {
        const float* Al = P.br[s].Al;
#pragma unroll
        for (int n = 0; n < NS; n++) A_[n] = -__expf(Al[e * NS + n]);
    }
    float h[NS], Pn[NS];
#pragma unroll
    for (int n = 0; n < NS; n++) { h[n] = 0.f; Pn[n] = 1.f; }
    float Rp = 1.f;
    const float* dptr = g_delta[s] + (size_t)(b * LSEQ + c * CLEN) * EDI + e;
    const float* xptr = g_xa[s]    + (size_t)(b * LSEQ + c * CLEN) * EDI + e;
    for (int t = 0; t < CLEN; t++) {
        float d = dptr[(size_t)t * EDI];
        float x = xptr[(size_t)t * EDI];
        float dx = d * x;
        if (fast) {
            float r = __expf(-d);
            Rp *= r;
            float dA = 1.f;
#pragma unroll
            for (int n = 0; n < NS; n++) {
                dA *= r;
                h[n] = fmaf(dA, h[n], dx * Bsm[t * NS + n]);
            }
        } else {
#pragma unroll
            for (int n = 0; n < NS; n++) {
                float dA = __expf(d * A_[n]);
                Pn[n] *= dA;
                h[n] = fmaf(dA, h[n], dx * Bsm[t * NS + n]);
            }
        }
    }
    if (fast) {
        float q = 1.f;
#pragma unroll
        for (int n = 0; n < NS; n++) { q *= Rp; Pn[n] = q; }
    }
    size_t base = (size_t)((s * BB + b) * NCHK + c) * 32 * EDI + e;
#pragma unroll
    for (int n = 0; n < NS; n++) g_sum[base + (size_t)n * EDI] = h[n];
#pragma unroll
    for (int n = 0; n < NS; n++) g_sum[base + (size_t)(16 + n) * EDI] = Pn[n];
}

// ------------------------- scan phase 2: chunk combine ----------------------
__global__ __launch_bounds__(512)
void scan2() {
    int s = blockIdx.x >> 1, b = blockIdx.x & 1;
    int e = threadIdx.x;
    float h[NS];
#pragma unroll
    for (int n = 0; n < NS; n++) h[n] = 0.f;
    for (int c = 0; c < NCHK; c++) {
        size_t sb = (size_t)((s * BB + b) * NCHK + c);
        size_t hb = sb * NS * EDI + e;
#pragma unroll
        for (int n = 0; n < NS; n++) g_h0[hb + (size_t)n * EDI] = h[n];
        size_t pb = sb * 32 * EDI + e;
#pragma unroll
        for (int n = 0; n < NS; n++) {
            float hl = g_sum[pb + (size_t)n * EDI];
            float Pv = g_sum[pb + (size_t)(16 + n) * EDI];
            h[n] = fmaf(Pv, h[n], hl);
        }
    }
}

// ------------------------- scan phase 3: full walk + gate -------------------
__global__ __launch_bounds__(512)
void scan3(AllPtrs P) {
    int blk = blockIdx.x;
    int s = blk / (BB * NCHK);
    int rem = blk % (BB * NCHK);
    int b = rem / NCHK, c = rem % NCHK;
    int e = threadIdx.x;
    __shared__ float Bsm[CLEN * NS];
    __shared__ float Csm[CLEN * NS];
    for (int idx = threadIdx.x; idx < CLEN * NS; idx += blockDim.x) {
        int t = idx / NS, n = idx % NS;
        int bl = b * LSEQ + c * CLEN + t;
        Bsm[idx] = g_dbc[s][(size_t)bl * DBCW + RRW + n];
        Csm[idx] = g_dbc[s][(size_t)bl * DBCW + RRW + NS + n];
    }
    __syncthreads();
    int fast = g_fast[s];
    float A_[NS];
    if (!fast) {
        const float* Al = P.br[s].Al;
#pragma unroll
        for (int n = 0; n < NS; n++) A_[n] = -__expf(Al[e * NS + n]);
    }
    float Dv = P.br[s].Dp[e];
    float h[NS];
    {
        size_t sb = (size_t)((s * BB + b) * NCHK + c);
        size_t hb = sb * NS * EDI + e;
#pragma unroll
        for (int n = 0; n < NS; n++) h[n] = g_h0[hb + (size_t)n * EDI];
    }
    for (int t = 0; t < CLEN; t++) {
        int l = c * CLEN + t;
        int bl = b * LSEQ + l;
        float d = g_delta[s][(size_t)bl * EDI + e];
        float x = g_xa[s][(size_t)bl * EDI + e];
        float dx = d * x;
        float acc = Dv * x;
        if (fast) {
            float r = __expf(-d);
            float dA = 1.f;
#pragma unroll
            for (int n = 0; n < NS; n++) {
                dA *= r;
                h[n] = fmaf(dA, h[n], dx * Bsm[t * NS + n]);
                acc = fmaf(h[n], Csm[t * NS + n], acc);
            }
        } else {
#pragma unroll
            for (int n = 0; n < NS; n++) {
                float dA = __expf(d * A_[n]);
                h[n] = fmaf(dA, h[n], dx * Bsm[t * NS + n]);
                acc = fmaf(h[n], Csm[t * NS + n], acc);
            }
        }
        int zr = b * LSEQ + in_row(s, l);
        float za = g_xz[(size_t)zr * ED2 + EDI + e];
        float sz = za / (1.f + __expf(-za));
        g_g[s][(size_t)bl * EDI + e] = acc * sz;
    }
}

// ------------------------- output combine (permutations + 0.25) -------------
__global__ __launch_bounds__(512)
void combine_kernel() {
    int bl = blockIdx.x;
    int b = bl / LSEQ, l = bl % LSEQ;
    int e = threadIdx.x;
    int rb = b * LSEQ + (LSEQ - 1 - l);
    int rc = b * LSEQ + pi_map(l);
    int rd = b * LSEQ + pi_map(LSEQ - 1 - l);
    g_y[(size_t)bl * EDI + e] = 0.25f * (g_g[0][(size_t)bl * EDI + e]
                                       + g_g[1][(size_t)rb * EDI + e]
                                       + g_g[2][(size_t)rc * EDI + e]
                                       + g_g[3][(size_t)rd * EDI + e]);
}

// ------------------------- launch ------------------------------------------
extern "C" void kernel_launch(void* const* d_in, const int* in_sizes, int n_in,
                              void* d_out, int out_size) {
    const float* x     = (const float*)d_in[0];
    const float* in_w  = (const float*)d_in[1];
    const float* out_w = (const float*)d_in[2];
    AllPtrs P;
    for (int s = 0; s < NBR; s++) {
        int o = 3 + 7 * s;
        P.br[s].cw  = (const float*)d_in[o + 0];
        P.br[s].cb  = (const float*)d_in[o + 1];
        P.br[s].xpw = (const float*)d_in[o + 2];
        P.br[s].dtw = (const float*)d_in[o + 3];
        P.br[s].dtb = (const float*)d_in[o + 4];
        P.br[s].Al  = (const float*)d_in[o + 5];
        P.br[s].Dp  = (const float*)d_in[o + 6];
    }
    float *p_xz, *p_xa, *p_dbc, *p_y;
    cudaGetSymbolAddress((void**)&p_xz,  g_xz);
    cudaGetSymbolAddress((void**)&p_xa,  g_xa);
    cudaGetSymbolAddress((void**)&p_dbc, g_dbc);
    cudaGetSymbolAddress((void**)&p_y,   g_y);

    flag_kernel<<<NBR, EDI>>>(P);

    // xz = x @ in_w^T : [2052,1024]
    sgemm_nt<<<dim3(ED2 / 64, (BLT + 63) / 64), 256>>>(x, in_w, p_xz, BLT, ED2, DMO);

    // per-branch permuted depthwise conv + SiLU
    conv_silu<<<NBR * BLT, EDI>>>(P);

    // dBC_s = xa_s @ xp_w_s^T : [2052,48]
    for (int s = 0; s < NBR; s++)
        sgemm_nt<<<dim3(1, (BLT + 63) / 64), 256>>>(
            p_xa + (size_t)s * BLT * EDI, P.br[s].xpw,
            p_dbc + (size_t)s * BLT * DBCW, BLT, DBCW, EDI);

    // delta
    delta_kernel<<<NBR * BLT, EDI>>>(P);

    // chunked selective scan
    scan1<<<NBR * BB * NCHK, EDI>>>(P);
    scan2<<<NBR * BB, EDI>>>();
    scan3<<<NBR * BB * NCHK, EDI>>>(P);

    // combine branch outputs with output permutations
    combine_kernel<<<BLT, EDI>>>();

    // out = y @ out_w^T : [2052,256]
    sgemm_nt<<<dim3(DMO / 64, (BLT + 63) / 64), 256>>>(p_y, out_w, (float*)d_out, BLT, DMO, EDI);
}

// round 2
// speedup vs baseline: 1.8327x; 1.8327x over previous
#include <cuda_runtime.h>
#include <math.h>
#include <stdint.h>

#define LSEQ 1026
#define BB   2
#define BLT  (BB*LSEQ)   // 2052
#define DMO  256
#define EDI  512
#define ED2  1024
#define NS   16
#define RRW  16
#define DBCW 48
#define NBR  4
#define NCHK 18
#define CLEN 57          // 18*57 = 1026

// ------------------------- scratch (device globals; no allocs) -------------
__device__ float g_xz[(size_t)BLT*ED2];
__device__ float g_xa[NBR][(size_t)BLT*EDI];
__device__ float g_dbc[NBR][(size_t)BLT*DBCW];
__device__ float g_delta[NBR][(size_t)BLT*EDI];
__device__ float g_sum[(size_t)NBR*BB*NCHK*32*EDI];
__device__ float g_h0[(size_t)NBR*BB*NCHK*NS*EDI];
__device__ float g_g[NBR][(size_t)BLT*EDI];
__device__ int   g_fast[NBR];

struct BranchPtrs { const float *cw,*cb,*xpw,*dtw,*dtb,*Al,*Dp; };
struct AllPtrs { BranchPtrs br[NBR]; };

// ------------------------- index maps ---------------------------------------
__device__ __forceinline__ int pi_map(int p) {
    if (p == 0 || p == LSEQ - 1) return p;
    int q = p - 1;
    int i = q >> 5, j = q & 31;
    return (j << 5) + i + 1;
}
__device__ __forceinline__ int in_row(int s, int p) {
    if (s == 0) return p;
    if (s == 1) return LSEQ - 1 - p;
    if (s == 2) return pi_map(p);
    return pi_map(LSEQ - 1 - p);
}

// ------------------------- generic SGEMM: C[m,n] = sum_k A[m,k]*B[n,k] ------
__global__ __launch_bounds__(256)
void sgemm_nt(const float* __restrict__ A, const float* __restrict__ Bm,
              float* __restrict__ C, int M, int N, int K) {
    __shared__ float As[16][64];
    __shared__ float Bs[16][64];
    int tid = threadIdx.x;
    int tx = tid & 15, ty = tid >> 4;
    int m0 = blockIdx.y * 64, n0 = blockIdx.x * 64;

    float acc[4][4];
#pragma unroll
    for (int i = 0; i < 4; i++)
#pragma unroll
        for (int j = 0; j < 4; j++) acc[i][j] = 0.f;

    int r = tid >> 2, kq = (tid & 3) * 4;
    for (int k0 = 0; k0 < K; k0 += 16) {
        float4 v = make_float4(0.f, 0.f, 0.f, 0.f);
        int m = m0 + r;
        if (m < M) v = *(const float4*)(A + (size_t)m * K + k0 + kq);
        As[kq + 0][r] = v.x; As[kq + 1][r] = v.y;
        As[kq + 2][r] = v.z; As[kq + 3][r] = v.w;
        float4 w = make_float4(0.f, 0.f, 0.f, 0.f);
        int n = n0 + r;
        if (n < N) w = *(const float4*)(Bm + (size_t)n * K + k0 + kq);
        Bs[kq + 0][r] = w.x; Bs[kq + 1][r] = w.y;
        Bs[kq + 2][r] = w.z; Bs[kq + 3][r] = w.w;
        __syncthreads();
#pragma unroll
        for (int k = 0; k < 16; k++) {
            float4 av = *(float4*)&As[k][ty * 4];
            float4 bv = *(float4*)&Bs[k][tx * 4];
            float a4[4] = {av.x, av.y, av.z, av.w};
            float b4[4] = {bv.x, bv.y, bv.z, bv.w};
#pragma unroll
            for (int i = 0; i < 4; i++)
#pragma unroll
                for (int j = 0; j < 4; j++)
                    acc[i][j] = fmaf(a4[i], b4[j], acc[i][j]);
        }
        __syncthreads();
    }
#pragma unroll
    for (int i = 0; i < 4; i++) {
        int m = m0 + ty * 4 + i;
        if (m >= M) continue;
#pragma unroll
        for (int j = 0; j < 4; j++) {
            int n = n0 + tx * 4 + j;
            if (n < N) C[(size_t)m * N + n] = acc[i][j];
        }
    }
}

// ----------- dBC: batched over branch + split-K(4), atomic accumulate -------
#define DBC_KS 4
#define DBC_KSL (EDI / DBC_KS)   // 128
__global__ __launch_bounds__(256)
void dbc_gemm(AllPtrs P) {
    __shared__ float As[16][64];
    __shared__ float Bs[16][64];
    int tid = threadIdx.x;
    int tx = tid & 15, ty = tid >> 4;
    int m0 = blockIdx.y * 64;
    int s  = blockIdx.z / DBC_KS;
    int kz = blockIdx.z % DBC_KS;
    const float* A  = g_xa[s];
    const float* Bm = P.br[s].xpw;
    float*       C  = g_dbc[s];

    float acc[4][4];
#pragma unroll
    for (int i = 0; i < 4; i++)
#pragma unroll
        for (int j = 0; j < 4; j++) acc[i][j] = 0.f;

    int r = tid >> 2, kq = (tid & 3) * 4;
    int kbeg = kz * DBC_KSL, kend = kbeg + DBC_KSL;
    for (int k0 = kbeg; k0 < kend; k0 += 16) {
        float4 v = make_float4(0.f, 0.f, 0.f, 0.f);
        int m = m0 + r;
        if (m < BLT) v = *(const float4*)(A + (size_t)m * EDI + k0 + kq);
        As[kq + 0][r] = v.x; As[kq + 1][r] = v.y;
        As[kq + 2][r] = v.z; As[kq + 3][r] = v.w;
        float4 w = make_float4(0.f, 0.f, 0.f, 0.f);
        if (r < DBCW) w = *(const float4*)(Bm + (size_t)r * EDI + k0 + kq);
        Bs[kq + 0][r] = w.x; Bs[kq + 1][r] = w.y;
        Bs[kq + 2][r] = w.z; Bs[kq + 3][r] = w.w;
        __syncthreads();
#pragma unroll
        for (int k = 0; k < 16; k++) {
            float4 av = *(float4*)&As[k][ty * 4];
            float4 bv = *(float4*)&Bs[k][tx * 4];
            float a4[4] = {av.x, av.y, av.z, av.w};
            float b4[4] = {bv.x, bv.y, bv.z, bv.w};
#pragma unroll
            for (int i = 0; i < 4; i++)
#pragma unroll
                for (int j = 0; j < 4; j++)
                    acc[i][j] = fmaf(a4[i], b4[j], acc[i][j]);
        }
        __syncthreads();
    }
#pragma unroll
    for (int i = 0; i < 4; i++) {
        int m = m0 + ty * 4 + i;
        if (m >= BLT) continue;
#pragma unroll
        for (int j = 0; j < 4; j++) {
            int n = tx * 4 + j;
            if (n < DBCW) atomicAdd(&C[(size_t)m * DBCW + n], acc[i][j]);
        }
    }
}

// ----- out-GEMM fused with branch combine (permutation gather), split-K(2) --
#define OUT_KS 2
#define OUT_KSL (EDI / OUT_KS)   // 256
__global__ __launch_bounds__(256)
void out_gemm_fused(const float* __restrict__ out_w, float* __restrict__ C) {
    __shared__ float As[16][64];
    __shared__ float Bs[16][64];
    int tid = threadIdx.x;
    int tx = tid & 15, ty = tid >> 4;
    int m0 = blockIdx.y * 64, n0 = blockIdx.x * 64;
    int kz = blockIdx.z;

    float acc[4][4];
#pragma unroll
    for (int i = 0; i < 4; i++)
#pragma unroll
        for (int j = 0; j < 4; j++) acc[i][j] = 0.f;

    int r = tid >> 2, kq = (tid & 3) * 4;
    // precompute gather rows for this thread's A row
    int m = m0 + r;
    size_t r0 = 0, r1 = 0, r2 = 0, r3 = 0;
    bool mval = (m < BLT);
    if (mval) {
        int b = m / LSEQ, l = m % LSEQ;
        r0 = (size_t)m * EDI;
        r1 = (size_t)(b * LSEQ + (LSEQ - 1 - l)) * EDI;
        r2 = (size_t)(b * LSEQ + pi_map(l)) * EDI;
        r3 = (size_t)(b * LSEQ + pi_map(LSEQ - 1 - l)) * EDI;
    }
    int kbeg = kz * OUT_KSL, kend = kbeg + OUT_KSL;
    for (int k0 = kbeg; k0 < kend; k0 += 16) {
        float4 v = make_float4(0.f, 0.f, 0.f, 0.f);
        if (mval) {
            int kk = k0 + kq;
            float4 a0 = *(const float4*)(g_g[0] + r0 + kk);
            float4 a1 = *(const float4*)(g_g[1] + r1 + kk);
            float4 a2 = *(const float4*)(g_g[2] + r2 + kk);
            float4 a3 = *(const float4*)(g_g[3] + r3 + kk);
            v.x = 0.25f * (a0.x + a1.x + a2.x + a3.x);
            v.y = 0.25f * (a0.y + a1.y + a2.y + a3.y);
            v.z = 0.25f * (a0.z + a1.z + a2.z + a3.z);
            v.w = 0.25f * (a0.w + a1.w + a2.w + a3.w);
        }
        As[kq + 0][r] = v.x; As[kq + 1][r] = v.y;
        As[kq + 2][r] = v.z; As[kq + 3][r] = v.w;
        float4 w = make_float4(0.f, 0.f, 0.f, 0.f);
        int n = n0 + r;
        if (n < DMO) w = *(const float4*)(out_w + (size_t)n * EDI + k0 + kq);
        Bs[kq + 0][r] = w.x; Bs[kq + 1][r] = w.y;
        Bs[kq + 2][r] = w.z; Bs[kq + 3][r] = w.w;
        __syncthreads();
#pragma unroll
        for (int k = 0; k < 16; k++) {
            float4 av = *(float4*)&As[k][ty * 4];
            float4 bv = *(float4*)&Bs[k][tx * 4];
            float a4[4] = {av.x, av.y, av.z, av.w};
            float b4[4] = {bv.x, bv.y, bv.z, bv.w};
#pragma unroll
            for (int i = 0; i < 4; i++)
#pragma unroll
                for (int j = 0; j < 4; j++)
                    acc[i][j] = fmaf(a4[i], b4[j], acc[i][j]);
        }
        __syncthreads();
    }
#pragma unroll
    for (int i = 0; i < 4; i++) {
        int mm = m0 + ty * 4 + i;
        if (mm >= BLT) continue;
#pragma unroll
        for (int j = 0; j < 4; j++) {
            int n = n0 + tx * 4 + j;
            atomicAdd(&C[(size_t)mm * DMO + n], acc[i][j]);
        }
    }
}

// ------------------------- structure check for A = -(n+1) -------------------
__global__ void flag_kernel(AllPtrs P) {
    __shared__ int ok;
    int s = blockIdx.x;
    if (threadIdx.x == 0) ok = 1;
    __syncthreads();
    const float* Al = P.br[s].Al;
    int e = threadIdx.x;
    bool good = true;
#pragma unroll
    for (int n = 0; n < NS; n++) {
        float ref = logf((float)(n + 1));
        if (fabsf(Al[e * NS + n] - ref) > 1e-5f * fmaxf(1.f, fabsf(ref))) good = false;
    }
    if (!good) atomicAnd(&ok, 0);
    __syncthreads();
    if (threadIdx.x == 0) g_fast[s] = ok;
}

// ------- depthwise conv (K=4 causal) + SiLU, rolling window over 6 pos ------
#define CONV_T 6
__global__ __launch_bounds__(512)
void conv_silu(AllPtrs P) {
    int blk = blockIdx.x;
    int ntile = LSEQ / CONV_T;           // 171
    int s  = blk / (BB * ntile);
    int rm = blk % (BB * ntile);
    int b  = rm / ntile;
    int l0 = (rm % ntile) * CONV_T;
    int e  = threadIdx.x;
    float4 cwv = *(const float4*)(P.br[s].cw + e * 4);
    float cb = P.br[s].cb[e];
    float v0 = 0.f, v1 = 0.f, v2 = 0.f;
    if (l0 >= 3) {
        v0 = g_xz[(size_t)(b * LSEQ + in_row(s, l0 - 3)) * ED2 + e];
        v1 = g_xz[(size_t)(b * LSEQ + in_row(s, l0 - 2)) * ED2 + e];
        v2 = g_xz[(size_t)(b * LSEQ + in_row(s, l0 - 1)) * ED2 + e];
    } else {
        if (l0 - 3 >= 0) v0 = g_xz[(size_t)(b * LSEQ + in_row(s, l0 - 3)) * ED2 + e];
        if (l0 - 2 >= 0) v1 = g_xz[(size_t)(b * LSEQ + in_row(s, l0 - 2)) * ED2 + e];
        if (l0 - 1 >= 0) v2 = g_xz[(size_t)(b * LSEQ + in_row(s, l0 - 1)) * ED2 + e];
    }
#pragma unroll
    for (int t = 0; t < CONV_T; t++) {
        int l = l0 + t;
        float v3 = g_xz[(size_t)(b * LSEQ + in_row(s, l)) * ED2 + e];
        float acc = cb;
        acc = fmaf(cwv.x, v0, acc);
        acc = fmaf(cwv.y, v1, acc);
        acc = fmaf(cwv.z, v2, acc);
        acc = fmaf(cwv.w, v3, acc);
        float sg = 1.f / (1.f + __expf(-acc));
        g_xa[s][(size_t)(b * LSEQ + l) * EDI + e] = acc * sg;
        v0 = v1; v1 = v2; v2 = v3;
    }
}

// -------- delta = softplus(dbc[:16] @ dtw^T + dtb), dtw staged in smem ------
#define DLT_ROWS 36
__global__ __launch_bounds__(512)
void delta_kernel(AllPtrs P) {
    __shared__ float dtw_s[EDI * 17];       // padded stride 17
    __shared__ float f_s[DLT_ROWS][RRW];
    int ntile = BLT / DLT_ROWS;             // 57
    int s  = blockIdx.x / ntile;
    int m0 = (blockIdx.x % ntile) * DLT_ROWS;
    int e  = threadIdx.x;
    const float* dtw = P.br[s].dtw;
    for (int idx = threadIdx.x; idx < EDI * RRW; idx += blockDim.x) {
        int ee = idx >> 4, q = idx & 15;
        dtw_s[ee * 17 + q] = dtw[idx];
    }
    for (int idx = threadIdx.x; idx < DLT_ROWS * RRW; idx += blockDim.x) {
        int rr = idx >> 4, q = idx & 15;
        f_s[rr][q] = g_dbc[s][(size_t)(m0 + rr) * DBCW + q];
    }
    __syncthreads();
    float dtb = P.br[s].dtb[e];
    float w[RRW];
#pragma unroll
    for (int q = 0; q < RRW; q++) w[q] = dtw_s[e * 17 + q];
    for (int rr = 0; rr < DLT_ROWS; rr++) {
        float u = dtb;
#pragma unroll
        for (int q = 0; q < RRW; q++) u = fmaf(f_s[rr][q], w[q], u);
        float d = fmaxf(u, 0.f) + log1pf(__expf(-fabsf(u)));
        g_delta[s][(size_t)(m0 + rr) * EDI + e] = d;
    }
}

// ------------------------- scan phase 1: chunk summaries --------------------
__global__ __launch_bounds__(512)
void scan1(AllPtrs P) {
    int blk = blockIdx.x;
    int s = blk / (BB * NCHK);
    int rem = blk % (BB * NCHK);
    int b = rem / NCHK, c = rem % NCHK;
    int e = threadIdx.x;
    __shared__ float Bsm[CLEN * NS];
    for (int idx = threadIdx.x; idx < CLEN * NS; idx += blockDim.x) {
        int t = idx / NS, n = idx % NS;
        int bl = b * LSEQ + c * CLEN + t;
        Bsm[idx] = g_dbc[s][(size_t)bl * DBCW + RRW + n];
    }
    __syncthreads();
    int fast = g_fast[s];
    float A_[NS];
    if (!fast) {
        const float* Al = P.br[s].Al;
#pragma unroll
        for (int n = 0; n < NS; n++) A_[n] = -__expf(Al[e * NS + n]);
    }
    float h[NS], Pn[NS];
#pragma unroll
    for (int n = 0; n < NS; n++) { h[n] = 0.f; Pn[n] = 1.f; }
    float Rp = 1.f;
    const float* dptr = g_delta[s] + (size_t)(b * LSEQ + c * CLEN) * EDI + e;
    const float* xptr = g_xa[s]    + (size_t)(b * LSEQ + c * CLEN) * EDI + e;
    for (int t = 0; t < CLEN; t++) {
        float d = dptr[(size_t)t * EDI];
        float x = xptr[(size_t)t * EDI];
        float dx = d * x;
        if (fast) {
            float r = __expf(-d);
            Rp *= r;
            float dA = 1.f;
#pragma unroll
            for (int n = 0; n < NS; n++) {
                dA *= r;
                h[n] = fmaf(dA, h[n], dx * Bsm[t * NS + n]);
            }
        } else {
#pragma unroll
            for (int n = 0; n < NS; n++) {
                float dA = __expf(d * A_[n]);
                Pn[n] *= dA;
                h[n] = fmaf(dA, h[n], dx * Bsm[t * NS + n]);
            }
        }
    }
    if (fast) {
        float q = 1.f;
#pragma unroll
        for (int n = 0; n < NS; n++) { q *= Rp; Pn[n] = q; }
    }
    size_t base = (size_t)((s * BB + b) * NCHK + c) * 32 * EDI + e;
#pragma unroll
    for (int n = 0; n < NS; n++) g_sum[base + (size_t)n * EDI] = h[n];
#pragma unroll
    for (int n = 0; n < NS; n++) g_sum[base + (size_t)(16 + n) * EDI] = Pn[n];
}

// ------------------------- scan phase 2: chunk combine ----------------------
__global__ __launch_bounds__(512)
void scan2() {
    int s = blockIdx.x >> 1, b = blockIdx.x & 1;
    int e = threadIdx.x;
    float h[NS];
#pragma unroll
    for (int n = 0; n < NS; n++) h[n] = 0.f;
    for (int c = 0; c < NCHK; c++) {
        size_t sb = (size_t)((s * BB + b) * NCHK + c);
        size_t hb = sb * NS * EDI + e;
#pragma unroll
        for (int n = 0; n < NS; n++) g_h0[hb + (size_t)n * EDI] = h[n];
        size_t pb = sb * 32 * EDI + e;
#pragma unroll
        for (int n = 0; n < NS; n++) {
            float hl = g_sum[pb + (size_t)n * EDI];
            float Pv = g_sum[pb + (size_t)(16 + n) * EDI];
            h[n] = fmaf(Pv, h[n], hl);
        }
    }
}

// ------------------------- scan phase 3: full walk + gate -------------------
__global__ __launch_bounds__(512)
void scan3(AllPtrs P) {
    int blk = blockIdx.x;
    int s = blk / (BB * NCHK);
    int rem = blk % (BB * NCHK);
    int b = rem / NCHK, c = rem % NCHK;
    int e = threadIdx.x;
    __shared__ float Bsm[CLEN * NS];
    __shared__ float Csm[CLEN * NS];
    for (int idx = threadIdx.x; idx < CLEN * NS; idx += blockDim.x) {
        int t = idx / NS, n = idx % NS;
        int bl = b * LSEQ + c * CLEN + t;
        Bsm[idx] = g_dbc[s][(size_t)bl * DBCW + RRW + n];
        Csm[idx] = g_dbc[s][(size_t)bl * DBCW + RRW + NS + n];
    }
    __syncthreads();
    int fast = g_fast[s];
    float A_[NS];
    if (!fast) {
        const float* Al = P.br[s].Al;
#pragma unroll
        for (int n = 0; n < NS; n++) A_[n] = -__expf(Al[e * NS + n]);
    }
    float Dv = P.br[s].Dp[e];
    float h[NS];
    {
        size_t sb = (size_t)((s * BB + b) * NCHK + c);
        size_t hb = sb * NS * EDI + e;
#pragma unroll
        for (int n = 0; n < NS; n++) h[n] = g_h0[hb + (size_t)n * EDI];
    }
    for (int t = 0; t < CLEN; t++) {
        int l = c * CLEN + t;
        int bl = b * LSEQ + l;
        float d = g_delta[s][(size_t)bl * EDI + e];
        float x = g_xa[s][(size_t)bl * EDI + e];
        float dx = d * x;
        float acc = Dv * x;
        if (fast) {
            float r = __expf(-d);
            float dA = 1.f;
#pragma unroll
            for (int n = 0; n < NS; n++) {
                dA *= r;
                h[n] = fmaf(dA, h[n], dx * Bsm[t * NS + n]);
                acc = fmaf(h[n], Csm[t * NS + n], acc);
            }
        } else {
#pragma unroll
            for (int n = 0; n < NS; n++) {
                float dA = __expf(d * A_[n]);
                h[n] = fmaf(dA, h[n], dx * Bsm[t * NS + n]);
                acc = fmaf(h[n], Csm[t * NS + n], acc);
            }
        }
        int zr = b * LSEQ + in_row(s, l);
        float za = g_xz[(size_t)zr * ED2 + EDI + e];
        float sz = za / (1.f + __expf(-za));
        g_g[s][(size_t)bl * EDI + e] = acc * sz;
    }
}

// ------------------------- launch ------------------------------------------
extern "C" void kernel_launch(void* const* d_in, const int* in_sizes, int n_in,
                              void* d_out, int out_size) {
    const float* x     = (const float*)d_in[0];
    const float* in_w  = (const float*)d_in[1];
    const float* out_w = (const float*)d_in[2];
    AllPtrs P;
    for (int s = 0; s < NBR; s++) {
        int o = 3 + 7 * s;
        P.br[s].cw  = (const float*)d_in[o + 0];
        P.br[s].cb  = (const float*)d_in[o + 1];
        P.br[s].xpw = (const float*)d_in[o + 2];
        P.br[s].dtw = (const float*)d_in[o + 3];
        P.br[s].dtb = (const float*)d_in[o + 4];
        P.br[s].Al  = (const float*)d_in[o + 5];
        P.br[s].Dp  = (const float*)d_in[o + 6];
    }
    float *p_xz, *p_dbc;
    cudaGetSymbolAddress((void**)&p_xz,  g_xz);
    cudaGetSymbolAddress((void**)&p_dbc, g_dbc);

    flag_kernel<<<NBR, EDI>>>(P);

    // xz = x @ in_w^T : [2052,1024]
    sgemm_nt<<<dim3(ED2 / 64, (BLT + 63) / 64), 256>>>(x, in_w, p_xz, BLT, ED2, DMO);

    // per-branch permuted depthwise conv + SiLU
    conv_silu<<<NBR * BB * (LSEQ / CONV_T), EDI>>>(P);

    // dBC: one batched split-K launch (528 blocks)
    cudaMemsetAsync(p_dbc, 0, (size_t)NBR * BLT * DBCW * sizeof(float));
    dbc_gemm<<<dim3(1, (BLT + 63) / 64, NBR * DBC_KS), 256>>>(P);

    // delta
    delta_kernel<<<NBR * (BLT / DLT_ROWS), EDI>>>(P);

    // chunked selective scan
    scan1<<<NBR * BB * NCHK, EDI>>>(P);
    scan2<<<NBR * BB, EDI>>>();
    scan3<<<NBR * BB * NCHK, EDI>>>(P);

    // fused combine + out-proj: out = (0.25*sum of permuted g) @ out_w^T
    cudaMemsetAsync(d_out, 0, (size_t)BLT * DMO * sizeof(float));
    out_gemm_fused<<<dim3(DMO / 64, (BLT + 63) / 64, OUT_KS), 256>>>(out_w, (float*)d_out);
}

// round 3
// speedup vs baseline: 2.2414x; 1.2230x over previous
#include <cuda_runtime.h>
#include <math.h>
#include <stdint.h>

#define LSEQ 1026
#define BB   2
#define BLT  (BB*LSEQ)   // 2052
#define DMO  256
#define EDI  512
#define ED2  1024
#define NS   16
#define RRW  16
#define DBCW 48
#define NBR  4
#define NCHK 18
#define CLEN 57          // 18*57 = 1026

// ------------------------- scratch (device globals; no allocs) -------------
__device__ float g_xz[(size_t)BLT*ED2];
__device__ float g_xa[NBR][(size_t)BLT*EDI];
__device__ float g_dbc[NBR][(size_t)BLT*DBCW];
__device__ float g_sum[(size_t)NBR*BB*NCHK*32*EDI];
__device__ float g_h0[(size_t)NBR*BB*NCHK*NS*EDI];
__device__ float g_g[NBR][(size_t)BLT*EDI];
__device__ int   g_fast[NBR];

struct BranchPtrs { const float *cw,*cb,*xpw,*dtw,*dtb,*Al,*Dp; };
struct AllPtrs { BranchPtrs br[NBR]; };

// ------------------------- index maps ---------------------------------------
__device__ __forceinline__ int pi_map(int p) {
    if (p == 0 || p == LSEQ - 1) return p;
    int q = p - 1;
    int i = q >> 5, j = q & 31;
    return (j << 5) + i + 1;
}
__device__ __forceinline__ int in_row(int s, int p) {
    if (s == 0) return p;
    if (s == 1) return LSEQ - 1 - p;
    if (s == 2) return pi_map(p);
    return pi_map(LSEQ - 1 - p);
}

// ============ 128x128 SGEMM (nt): C[m,n] = sum_k A[m,k]*B[n,k] ==============
__global__ __launch_bounds__(256)
void sgemm_nt_big(const float* __restrict__ A, const float* __restrict__ Bm,
                  float* __restrict__ C, int M, int N, int K) {
    __shared__ float As[16][128];
    __shared__ float Bs[16][128];
    int tid = threadIdx.x;
    int tx = tid & 15, ty = tid >> 4;
    int m0 = blockIdx.y * 128, n0 = blockIdx.x * 128;
    int srow = tid >> 1;
    int skq  = (tid & 1) * 8;
    bool mok = (m0 + srow) < M;
    bool nok = (n0 + srow) < N;
    const float* Ap = A + (size_t)(m0 + srow) * K + skq;
    const float* Bp = Bm + (size_t)(n0 + srow) * K + skq;

    float4 a0 = make_float4(0,0,0,0), a1 = a0, b0 = a0, b1 = a0;
    if (mok) { a0 = *(const float4*)Ap; a1 = *(const float4*)(Ap + 4); }
    if (nok) { b0 = *(const float4*)Bp; b1 = *(const float4*)(Bp + 4); }
    Ap += 16; Bp += 16;

    float acc[8][8];
#pragma unroll
    for (int i = 0; i < 8; i++)
#pragma unroll
        for (int j = 0; j < 8; j++) acc[i][j] = 0.f;

    int nchunk = K >> 4;
    for (int c = 0; c < nchunk; c++) {
        As[skq+0][srow]=a0.x; As[skq+1][srow]=a0.y; As[skq+2][srow]=a0.z; As[skq+3][srow]=a0.w;
        As[skq+4][srow]=a1.x; As[skq+5][srow]=a1.y; As[skq+6][srow]=a1.z; As[skq+7][srow]=a1.w;
        Bs[skq+0][srow]=b0.x; Bs[skq+1][srow]=b0.y; Bs[skq+2][srow]=b0.z; Bs[skq+3][srow]=b0.w;
        Bs[skq+4][srow]=b1.x; Bs[skq+5][srow]=b1.y; Bs[skq+6][srow]=b1.z; Bs[skq+7][srow]=b1.w;
        __syncthreads();
        if (c + 1 < nchunk) {
            a0 = make_float4(0,0,0,0); a1 = a0; b0 = a0; b1 = a0;
            if (mok) { a0 = *(const float4*)Ap; a1 = *(const float4*)(Ap + 4); }
            if (nok) { b0 = *(const float4*)Bp; b1 = *(const float4*)(Bp + 4); }
            Ap += 16; Bp += 16;
        }
#pragma unroll
        for (int k = 0; k < 16; k++) {
            float4 av0 = *(float4*)&As[k][ty*4];
            float4 av1 = *(float4*)&As[k][64 + ty*4];
            float4 bv0 = *(float4*)&Bs[k][tx*4];
            float4 bv1 = *(float4*)&Bs[k][64 + tx*4];
            float a4[8] = {av0.x,av0.y,av0.z,av0.w, av1.x,av1.y,av1.z,av1.w};
            float b4[8] = {bv0.x,bv0.y,bv0.z,bv0.w, bv1.x,bv1.y,bv1.z,bv1.w};
#pragma unroll
            for (int i = 0; i < 8; i++)
#pragma unroll
                for (int j = 0; j < 8; j++)
                    acc[i][j] = fmaf(a4[i], b4[j], acc[i][j]);
        }
        __syncthreads();
    }
#pragma unroll
    for (int i = 0; i < 8; i++) {
        int m = m0 + (i >> 2) * 64 + ty * 4 + (i & 3);
        if (m >= M) continue;
#pragma unroll
        for (int j = 0; j < 8; j++) {
            int n = n0 + (j >> 2) * 64 + tx * 4 + (j & 3);
            if (n < N) C[(size_t)m * N + n] = acc[i][j];
        }
    }
}

// ============ dBC: 128x48 tile, batched branches + split-K(4) ===============
#define DBC_KS 4
__global__ __launch_bounds__(256)
void dbc_gemm(AllPtrs P) {
    __shared__ float As[16][128];
    __shared__ float Bs[16][48];
    int tid = threadIdx.x;
    int tx = tid & 15, ty = tid >> 4;
    int m0 = blockIdx.y * 128;
    int s  = blockIdx.z >> 2;
    int kz = blockIdx.z & 3;
    const float* A  = g_xa[s];
    const float* Bm = P.br[s].xpw;
    float*       C  = g_dbc[s];

    int srow = tid >> 1;
    int skq  = (tid & 1) * 8;
    bool mok = (m0 + srow) < BLT;
    const float* Ap = A + (size_t)(m0 + srow) * EDI + kz * 128 + skq;
    int brow = tid >> 2, bkq = (tid & 3) * 4;
    bool bok = tid < 192;
    const float* Bp = Bm + (size_t)brow * EDI + kz * 128 + bkq;

    float4 a0 = make_float4(0,0,0,0), a1 = a0, b0 = a0;
    if (mok) { a0 = *(const float4*)Ap; a1 = *(const float4*)(Ap + 4); }
    if (bok) b0 = *(const float4*)Bp;
    Ap += 16; Bp += 16;

    float acc[8][3];
#pragma unroll
    for (int i = 0; i < 8; i++)
#pragma unroll
        for (int j = 0; j < 3; j++) acc[i][j] = 0.f;

    for (int c = 0; c < 8; c++) {
        As[skq+0][srow]=a0.x; As[skq+1][srow]=a0.y; As[skq+2][srow]=a0.z; As[skq+3][srow]=a0.w;
        As[skq+4][srow]=a1.x; As[skq+5][srow]=a1.y; As[skq+6][srow]=a1.z; As[skq+7][srow]=a1.w;
        if (bok) {
            Bs[bkq+0][brow]=b0.x; Bs[bkq+1][brow]=b0.y;
            Bs[bkq+2][brow]=b0.z; Bs[bkq+3][brow]=b0.w;
        }
        __syncthreads();
        if (c + 1 < 8) {
            a0 = make_float4(0,0,0,0); a1 = a0; b0 = a0;
            if (mok) { a0 = *(const float4*)Ap; a1 = *(const float4*)(Ap + 4); }
            if (bok) b0 = *(const float4*)Bp;
            Ap += 16; Bp += 16;
        }
#pragma unroll
        for (int k = 0; k < 16; k++) {
            float4 av0 = *(float4*)&As[k][ty*4];
            float4 av1 = *(float4*)&As[k][64 + ty*4];
            float a4[8] = {av0.x,av0.y,av0.z,av0.w, av1.x,av1.y,av1.z,av1.w};
            float b4[3] = {Bs[k][tx*3], Bs[k][tx*3+1], Bs[k][tx*3+2]};
#pragma unroll
            for (int i = 0; i < 8; i++)
#pragma unroll
                for (int j = 0; j < 3; j++)
                    acc[i][j] = fmaf(a4[i], b4[j], acc[i][j]);
        }
        __syncthreads();
    }
#pragma unroll
    for (int i = 0; i < 8; i++) {
        int m = m0 + (i >> 2) * 64 + ty * 4 + (i & 3);
        if (m >= BLT) continue;
#pragma unroll
        for (int j = 0; j < 3; j++)
            atomicAdd(&C[(size_t)m * DBCW + tx * 3 + j], acc[i][j]);
    }
}

// ===== out-GEMM fused with branch combine (permutation gather), splitK ======
#define OUT_KS 4
__global__ __launch_bounds__(256)
void out_gemm_fused(const float* __restrict__ out_w, float* __restrict__ C) {
    __shared__ float As[16][128];
    __shared__ float Bs[16][128];
    int tid = threadIdx.x;
    int tx = tid & 15, ty = tid >> 4;
    int m0 = blockIdx.y * 128, n0 = blockIdx.x * 128;
    int kz = blockIdx.z;
    int srow = tid >> 1;
    int skq  = (tid & 1) * 8;
    int m = m0 + srow;
    bool mok = m < BLT;
    size_t r0 = 0, r1 = 0, r2 = 0, r3 = 0;
    if (mok) {
        int b = m / LSEQ, l = m % LSEQ;
        r0 = (size_t)m * EDI;
        r1 = (size_t)(b * LSEQ + (LSEQ - 1 - l)) * EDI;
        r2 = (size_t)(b * LSEQ + pi_map(l)) * EDI;
        r3 = (size_t)(b * LSEQ + pi_map(LSEQ - 1 - l)) * EDI;
    }
    const float* Bp = out_w + (size_t)(n0 + srow) * EDI + kz * 128 + skq;

    float4 a0, a1, b0, b1;
    int kk = kz * 128 + skq;
    a0 = make_float4(0,0,0,0); a1 = a0;
    if (mok) {
        float4 p0 = *(const float4*)(g_g[0]+r0+kk), p1 = *(const float4*)(g_g[1]+r1+kk);
        float4 p2 = *(const float4*)(g_g[2]+r2+kk), p3 = *(const float4*)(g_g[3]+r3+kk);
        a0.x = 0.25f*(p0.x+p1.x+p2.x+p3.x); a0.y = 0.25f*(p0.y+p1.y+p2.y+p3.y);
        a0.z = 0.25f*(p0.z+p1.z+p2.z+p3.z); a0.w = 0.25f*(p0.w+p1.w+p2.w+p3.w);
        float4 q0 = *(const float4*)(g_g[0]+r0+kk+4), q1 = *(const float4*)(g_g[1]+r1+kk+4);
        float4 q2 = *(const float4*)(g_g[2]+r2+kk+4), q3 = *(const float4*)(g_g[3]+r3+kk+4);
        a1.x = 0.25f*(q0.x+q1.x+q2.x+q3.x); a1.y = 0.25f*(q0.y+q1.y+q2.y+q3.y);
        a1.z = 0.25f*(q0.z+q1.z+q2.z+q3.z); a1.w = 0.25f*(q0.w+q1.w+q2.w+q3.w);
    }
    b0 = *(const float4*)Bp; b1 = *(const float4*)(Bp + 4);
    Bp += 16;

    float acc[8][8];
#pragma unroll
    for (int i = 0; i < 8; i++)
#pragma unroll
        for (int j = 0; j < 8; j++) acc[i][j] = 0.f;

    for (int c = 0; c < 8; c++) {
        As[skq+0][srow]=a0.x; As[skq+1][srow]=a0.y; As[skq+2][srow]=a0.z; As[skq+3][srow]=a0.w;
        As[skq+4][srow]=a1.x; As[skq+5][srow]=a1.y; As[skq+6][srow]=a1.z; As[skq+7][srow]=a1.w;
        Bs[skq+0][srow]=b0.x; Bs[skq+1][srow]=b0.y; Bs[skq+2][srow]=b0.z; Bs[skq+3][srow]=b0.w;
        Bs[skq+4][srow]=b1.x; Bs[skq+5][srow]=b1.y; Bs[skq+6][srow]=b1.z; Bs[skq+7][srow]=b1.w;
        __syncthreads();
        if (c + 1 < 8) {
            kk = kz * 128 + (c + 1) * 16 + skq;
            a0 = make_float4(0,0,0,0); a1 = a0;
            if (mok) {
                float4 p0 = *(const float4*)(g_g[0]+r0+kk), p1 = *(const float4*)(g_g[1]+r1+kk);
                float4 p2 = *(const float4*)(g_g[2]+r2+kk), p3 = *(const float4*)(g_g[3]+r3+kk);
                a0.x = 0.25f*(p0.x+p1.x+p2.x+p3.x); a0.y = 0.25f*(p0.y+p1.y+p2.y+p3.y);
                a0.z = 0.25f*(p0.z+p1.z+p2.z+p3.z); a0.w = 0.25f*(p0.w+p1.w+p2.w+p3.w);
                float4 q0 = *(const float4*)(g_g[0]+r0+kk+4), q1 = *(const float4*)(g_g[1]+r1+kk+4);
                float4 q2 = *(const float4*)(g_g[2]+r2+kk+4), q3 = *(const float4*)(g_g[3]+r3+kk+4);
                a1.x = 0.25f*(q0.x+q1.x+q2.x+q3.x); a1.y = 0.25f*(q0.y+q1.y+q2.y+q3.y);
                a1.z = 0.25f*(q0.z+q1.z+q2.z+q3.z); a1.w = 0.25f*(q0.w+q1.w+q2.w+q3.w);
            }
            b0 = *(const float4*)Bp; b1 = *(const float4*)(Bp + 4);
            Bp += 16;
        }
#pragma unroll
        for (int k = 0; k < 16; k++) {
            float4 av0 = *(float4*)&As[k][ty*4];
            float4 av1 = *(float4*)&As[k][64 + ty*4];
            float4 bv0 = *(float4*)&Bs[k][tx*4];
            float4 bv1 = *(float4*)&Bs[k][64 + tx*4];
            float a4[8] = {av0.x,av0.y,av0.z,av0.w, av1.x,av1.y,av1.z,av1.w};
            float b4[8] = {bv0.x,bv0.y,bv0.z,bv0.w, bv1.x,bv1.y,bv1.z,bv1.w};
#pragma unroll
            for (int i = 0; i < 8; i++)
#pragma unroll
                for (int j = 0; j < 8; j++)
                    acc[i][j] = fmaf(a4[i], b4[j], acc[i][j]);
        }
        __syncthreads();
    }
#pragma unroll
    for (int i = 0; i < 8; i++) {
        int mm = m0 + (i >> 2) * 64 + ty * 4 + (i & 3);
        if (mm >= BLT) continue;
#pragma unroll
        for (int j = 0; j < 8; j++) {
            int n = n0 + (j >> 2) * 64 + tx * 4 + (j & 3);
            atomicAdd(&C[(size_t)mm * DMO + n], acc[i][j]);
        }
    }
}

// ------------------------- structure check for A = -(n+1) -------------------
__global__ void flag_kernel(AllPtrs P) {
    __shared__ int ok;
    int s = blockIdx.x;
    if (threadIdx.x == 0) ok = 1;
    __syncthreads();
    const float* Al = P.br[s].Al;
    int e = threadIdx.x;
    bool good = true;
#pragma unroll
    for (int n = 0; n < NS; n++) {
        float ref = logf((float)(n + 1));
        if (fabsf(Al[e * NS + n] - ref) > 1e-5f * fmaxf(1.f, fabsf(ref))) good = false;
    }
    if (!good) atomicAnd(&ok, 0);
    __syncthreads();
    if (threadIdx.x == 0) g_fast[s] = ok;
}

// ------- depthwise conv (K=4 causal) + SiLU, rolling window over 6 pos ------
#define CONV_T 6
__global__ __launch_bounds__(512)
void conv_silu(AllPtrs P) {
    int blk = blockIdx.x;
    int ntile = LSEQ / CONV_T;           // 171
    int s  = blk / (BB * ntile);
    int rm = blk % (BB * ntile);
    int b  = rm / ntile;
    int l0 = (rm % ntile) * CONV_T;
    int e  = threadIdx.x;
    float4 cwv = *(const float4*)(P.br[s].cw + e * 4);
    float cb = P.br[s].cb[e];
    float v0 = 0.f, v1 = 0.f, v2 = 0.f;
    if (l0 - 3 >= 0) v0 = g_xz[(size_t)(b * LSEQ + in_row(s, l0 - 3)) * ED2 + e];
    if (l0 - 2 >= 0) v1 = g_xz[(size_t)(b * LSEQ + in_row(s, l0 - 2)) * ED2 + e];
    if (l0 - 1 >= 0) v2 = g_xz[(size_t)(b * LSEQ + in_row(s, l0 - 1)) * ED2 + e];
#pragma unroll
    for (int t = 0; t < CONV_T; t++) {
        int l = l0 + t;
        float v3 = g_xz[(size_t)(b * LSEQ + in_row(s, l)) * ED2 + e];
        float acc = cb;
        acc = fmaf(cwv.x, v0, acc);
        acc = fmaf(cwv.y, v1, acc);
        acc = fmaf(cwv.z, v2, acc);
        acc = fmaf(cwv.w, v3, acc);
        float sg = 1.f / (1.f + __expf(-acc));
        g_xa[s][(size_t)(b * LSEQ + l) * EDI + e] = acc * sg;
        v0 = v1; v1 = v2; v2 = v3;
    }
}

// -------- scan phase 1: chunk summaries, delta fused in ---------------------
__global__ __launch_bounds__(512)
void scan1(AllPtrs P) {
    __shared__ float dtw_s[EDI * 17];
    __shared__ float f_s[CLEN][NS];
    __shared__ float Bsm[CLEN * NS];
    int blk = blockIdx.x;
    int s = blk / (BB * NCHK);
    int rem = blk % (BB * NCHK);
    int b = rem / NCHK, c = rem % NCHK;
    int e = threadIdx.x;
    const float* dtw = P.br[s].dtw;
    for (int idx = threadIdx.x; idx < EDI * RRW; idx += blockDim.x)
        dtw_s[(idx >> 4) * 17 + (idx & 15)] = dtw[idx];
    for (int idx = threadIdx.x; idx < CLEN * 32; idx += blockDim.x) {
        int t = idx >> 5, q = idx & 31;
        float v = g_dbc[s][(size_t)(b * LSEQ + c * CLEN + t) * DBCW + q];
        if (q < 16) f_s[t][q] = v;
        else        Bsm[t * NS + (q - 16)] = v;
    }
    __syncthreads();
    float w[RRW];
#pragma unroll
    for (int q = 0; q < RRW; q++) w[q] = dtw_s[e * 17 + q];
    float dtb = P.br[s].dtb[e];
    int fast = g_fast[s];
    float A_[NS];
    if (!fast) {
        const float* Al = P.br[s].Al;
#pragma unroll
        for (int n = 0; n < NS; n++) A_[n] = -__expf(Al[e * NS + n]);
    }
    float h[NS], Pn[NS];
#pragma unroll
    for (int n = 0; n < NS; n++) { h[n] = 0.f; Pn[n] = 1.f; }
    float Rp = 1.f;
    const float* xptr = g_xa[s] + (size_t)(b * LSEQ + c * CLEN) * EDI + e;
    for (int t = 0; t < CLEN; t++) {
        float u = dtb;
#pragma unroll
        for (int q = 0; q < RRW; q++) u = fmaf(f_s[t][q], w[q], u);
        float d = fmaxf(u, 0.f) + log1pf(__expf(-fabsf(u)));
        float x = xptr[(size_t)t * EDI];
        float dx = d * x;
        if (fast) {
            float r = __expf(-d);
            Rp *= r;
            float dA = 1.f;
#pragma unroll
            for (int n = 0; n < NS; n++) {
                dA *= r;
                h[n] = fmaf(dA, h[n], dx * Bsm[t * NS + n]);
            }
        } else {
#pragma unroll
            for (int n = 0; n < NS; n++) {
                float dA = __expf(d * A_[n]);
                Pn[n] *= dA;
                h[n] = fmaf(dA, h[n], dx * Bsm[t * NS + n]);
            }
        }
    }
    if (fast) {
        float q = 1.f;
#pragma unroll
        for (int n = 0; n < NS; n++) { q *= Rp; Pn[n] = q; }
    }
    size_t base = (size_t)((s * BB + b) * NCHK + c) * 32 * EDI + e;
#pragma unroll
    for (int n = 0; n < NS; n++) g_sum[base + (size_t)n * EDI] = h[n];
#pragma unroll
    for (int n = 0; n < NS; n++) g_sum[base + (size_t)(16 + n) * EDI] = Pn[n];
}

// ------------------------- scan phase 2: chunk combine ----------------------
__global__ __launch_bounds__(512)
void scan2() {
    int s = blockIdx.x >> 1, b = blockIdx.x & 1;
    int e = threadIdx.x;
    float h[NS];
#pragma unroll
    for (int n = 0; n < NS; n++) h[n] = 0.f;
    for (int c = 0; c < NCHK; c++) {
        size_t sb = (size_t)((s * BB + b) * NCHK + c);
        size_t hb = sb * NS * EDI + e;
#pragma unroll
        for (int n = 0; n < NS; n++) g_h0[hb + (size_t)n * EDI] = h[n];
        size_t pb = sb * 32 * EDI + e;
#pragma unroll
        for (int n = 0; n < NS; n++) {
            float hl = g_sum[pb + (size_t)n * EDI];
            float Pv = g_sum[pb + (size_t)(16 + n) * EDI];
            h[n] = fmaf(Pv, h[n], hl);
        }
    }
}

// -------- scan phase 3: full walk + gate, delta fused in --------------------
__global__ __launch_bounds__(512)
void scan3(AllPtrs P) {
    __shared__ float dtw_s[EDI * 17];
    __shared__ float f_s[CLEN][NS];
    __shared__ float Bsm[CLEN * NS];
    __shared__ float Csm[CLEN * NS];
    int blk = blockIdx.x;
    int s = blk / (BB * NCHK);
    int rem = blk % (BB * NCHK);
    int b = rem / NCHK, c = rem % NCHK;
    int e = threadIdx.x;
    const float* dtw = P.br[s].dtw;
    for (int idx = threadIdx.x; idx < EDI * RRW; idx += blockDim.x)
        dtw_s[(idx >> 4) * 17 + (idx & 15)] = dtw[idx];
    for (int idx = threadIdx.x; idx < CLEN * DBCW; idx += blockDim.x) {
        int t = idx / DBCW, q = idx % DBCW;
        float v = g_dbc[s][(size_t)(b * LSEQ + c * CLEN + t) * DBCW + q];
        if (q < 16)      f_s[t][q] = v;
        else if (q < 32) Bsm[t * NS + (q - 16)] = v;
        else             Csm[t * NS + (q - 32)] = v;
    }
    __syncthreads();
    float w[RRW];
#pragma unroll
    for (int q = 0; q < RRW; q++) w[q] = dtw_s[e * 17 + q];
    float dtb = P.br[s].dtb[e];
    int fast = g_fast[s];
    float A_[NS];
    if (!fast) {
        const float* Al = P.br[s].Al;
#pragma unroll
        for (int n = 0; n < NS; n++) A_[n] = -__expf(Al[e * NS + n]);
    }
    float Dv = P.br[s].Dp[e];
    float h[NS];
    {
        size_t sb = (size_t)((s * BB + b) * NCHK + c);
        size_t hb = sb * NS * EDI + e;
#pragma unroll
        for (int n = 0; n < NS; n++) h[n] = g_h0[hb + (size_t)n * EDI];
    }
    for (int t = 0; t < CLEN; t++) {
        int l = c * CLEN + t;
        int bl = b * LSEQ + l;
        float u = dtb;
#pragma unroll
        for (int q = 0; q < RRW; q++) u = fmaf(f_s[t][q], w[q], u);
        float d = fmaxf(u, 0.f) + log1pf(__expf(-fabsf(u)));
        float x = g_xa[s][(size_t)bl * EDI + e];
        float dx = d * x;
        float acc = Dv * x;
        if (fast) {
            float r = __expf(-d);
            float dA = 1.f;
#pragma unroll
            for (int n = 0; n < NS; n++) {
                dA *= r;
                h[n] = fmaf(dA, h[n], dx * Bsm[t * NS + n]);
                acc = fmaf(h[n], Csm[t * NS + n], acc);
            }
        } else {
#pragma unroll
            for (int n = 0; n < NS; n++) {
                float dA = __expf(d * A_[n]);
                h[n] = fmaf(dA, h[n], dx * Bsm[t * NS + n]);
                acc = fmaf(h[n], Csm[t * NS + n], acc);
            }
        }
        int zr = b * LSEQ + in_row(s, l);
        float za = g_xz[(size_t)zr * ED2 + EDI + e];
        float sz = za / (1.f + __expf(-za));
        g_g[s][(size_t)bl * EDI + e] = acc * sz;
    }
}

// ------------------------- launch ------------------------------------------
extern "C" void kernel_launch(void* const* d_in, const int* in_sizes, int n_in,
                              void* d_out, int out_size) {
    const float* x     = (const float*)d_in[0];
    const float* in_w  = (const float*)d_in[1];
    const float* out_w = (const float*)d_in[2];
    AllPtrs P;
    for (int s = 0; s < NBR; s++) {
        int o = 3 + 7 * s;
        P.br[s].cw  = (const float*)d_in[o + 0];
        P.br[s].cb  = (const float*)d_in[o + 1];
        P.br[s].xpw = (const float*)d_in[o + 2];
        P.br[s].dtw = (const float*)d_in[o + 3];
        P.br[s].dtb = (const float*)d_in[o + 4];
        P.br[s].Al  = (const float*)d_in[o + 5];
        P.br[s].Dp  = (const float*)d_in[o + 6];
    }
    float *p_xz, *p_dbc;
    cudaGetSymbolAddress((void**)&p_xz,  g_xz);
    cudaGetSymbolAddress((void**)&p_dbc, g_dbc);

    flag_kernel<<<NBR, EDI>>>(P);

    // xz = x @ in_w^T : [2052,1024], K=256
    sgemm_nt_big<<<dim3(ED2 / 128, (BLT + 127) / 128), 256>>>(x, in_w, p_xz, BLT, ED2, DMO);

    // per-branch permuted depthwise conv + SiLU
    conv_silu<<<NBR * BB * (LSEQ / CONV_T), EDI>>>(P);

    // dBC: batched split-K launch
    cudaMemsetAsync(p_dbc, 0, (size_t)NBR * BLT * DBCW * sizeof(float));
    dbc_gemm<<<dim3(1, (BLT + 127) / 128, NBR * DBC_KS), 256>>>(P);

    // chunked selective scan (delta fused)
    scan1<<<NBR * BB * NCHK, EDI>>>(P);
    scan2<<<NBR * BB, EDI>>>();
    scan3<<<NBR * BB * NCHK, EDI>>>(P);

    // fused combine + out-proj
    cudaMemsetAsync(d_out, 0, (size_t)BLT * DMO * sizeof(float));
    out_gemm_fused<<<dim3(DMO / 128, (BLT + 127) / 128, OUT_KS), 256>>>(out_w, (float*)d_out);
}

// round 4
// speedup vs baseline: 2.5474x; 1.1365x over previous
#include <cuda_runtime.h>
#include <math.h>
#include <stdint.h>

#define LSEQ 1026
#define BB   2
#define BLT  (BB*LSEQ)   // 2052
#define DMO  256
#define EDI  512
#define ED2  1024
#define NS   16
#define RRW  16
#define DBCW 48
#define NBR  4
#define NCHK 18
#define CLEN 57          // 18*57 = 1026
#define EHALF 256

// ------------------------- scratch (device globals; no allocs) -------------
__device__ float g_xz[(size_t)BLT*ED2];
__device__ float g_xa[NBR][(size_t)BLT*EDI];
__device__ float g_dbc[NBR][(size_t)BLT*DBCW];
__device__ float g_sum[(size_t)NBR*BB*NCHK*32*EDI];
__device__ float g_h0[(size_t)NBR*BB*NCHK*NS*EDI];
__device__ float g_g[NBR][(size_t)BLT*EDI];
__device__ int   g_fast[NBR];

struct BranchPtrs { const float *cw,*cb,*xpw,*dtw,*dtb,*Al,*Dp; };
struct AllPtrs { BranchPtrs br[NBR]; };

// ------------------------- index maps ---------------------------------------
__device__ __forceinline__ int pi_map(int p) {
    if (p == 0 || p == LSEQ - 1) return p;
    int q = p - 1;
    int i = q >> 5, j = q & 31;
    return (j << 5) + i + 1;
}
__device__ __forceinline__ int in_row(int s, int p) {
    if (s == 0) return p;
    if (s == 1) return LSEQ - 1 - p;
    if (s == 2) return pi_map(p);
    return pi_map(LSEQ - 1 - p);
}

// ============ 128x64 SGEMM (nt): C[m,n] = sum_k A[m,k]*B[n,k] ===============
// 256 threads, 8x4 per thread. grid.x = N/64, grid.y = ceil(M/128).
__global__ __launch_bounds__(256)
void sgemm_nt_12864(const float* __restrict__ A, const float* __restrict__ Bm,
                    float* __restrict__ C, int M, int N, int K) {
    __shared__ float As[16][128];
    __shared__ float Bs[16][64];
    int tid = threadIdx.x;
    int tx = tid & 15, ty = tid >> 4;
    int m0 = blockIdx.y * 128, n0 = blockIdx.x * 64;
    int srow = tid >> 1;
    int skq  = (tid & 1) * 8;
    bool mok = (m0 + srow) < M;
    const float* Ap = A + (size_t)(m0 + srow) * K + skq;
    int brow = tid >> 2, bkq = (tid & 3) * 4;
    const float* Bp = Bm + (size_t)(n0 + brow) * K + bkq;

    float4 a0 = make_float4(0,0,0,0), a1 = a0, b0 = a0;
    if (mok) { a0 = *(const float4*)Ap; a1 = *(const float4*)(Ap + 4); }
    b0 = *(const float4*)Bp;
    Ap += 16; Bp += 16;

    float acc[8][4];
#pragma unroll
    for (int i = 0; i < 8; i++)
#pragma unroll
        for (int j = 0; j < 4; j++) acc[i][j] = 0.f;

    int nchunk = K >> 4;
    for (int c = 0; c < nchunk; c++) {
        As[skq+0][srow]=a0.x; As[skq+1][srow]=a0.y; As[skq+2][srow]=a0.z; As[skq+3][srow]=a0.w;
        As[skq+4][srow]=a1.x; As[skq+5][srow]=a1.y; As[skq+6][srow]=a1.z; As[skq+7][srow]=a1.w;
        Bs[bkq+0][brow]=b0.x; Bs[bkq+1][brow]=b0.y; Bs[bkq+2][brow]=b0.z; Bs[bkq+3][brow]=b0.w;
        __syncthreads();
        if (c + 1 < nchunk) {
            a0 = make_float4(0,0,0,0); a1 = a0;
            if (mok) { a0 = *(const float4*)Ap; a1 = *(const float4*)(Ap + 4); }
            b0 = *(const float4*)Bp;
            Ap += 16; Bp += 16;
        }
#pragma unroll
        for (int k = 0; k < 16; k++) {
            float4 av0 = *(float4*)&As[k][ty*4];
            float4 av1 = *(float4*)&As[k][64 + ty*4];
            float4 bv0 = *(float4*)&Bs[k][tx*4];
            float a4[8] = {av0.x,av0.y,av0.z,av0.w, av1.x,av1.y,av1.z,av1.w};
            float b4[4] = {bv0.x,bv0.y,bv0.z,bv0.w};
#pragma unroll
            for (int i = 0; i < 8; i++)
#pragma unroll
                for (int j = 0; j < 4; j++)
                    acc[i][j] = fmaf(a4[i], b4[j], acc[i][j]);
        }
        __syncthreads();
    }
#pragma unroll
    for (int i = 0; i < 8; i++) {
        int m = m0 + (i >> 2) * 64 + ty * 4 + (i & 3);
        if (m >= M) continue;
#pragma unroll
        for (int j = 0; j < 4; j++) {
            int n = n0 + tx * 4 + j;
            C[(size_t)m * N + n] = acc[i][j];
        }
    }
}

// ============ dBC: 128x48 tile, batched branches + split-K(8) ===============
#define DBC_KS 8
#define DBC_KL (EDI / DBC_KS)   // 64
__global__ __launch_bounds__(256)
void dbc_gemm(AllPtrs P) {
    __shared__ float As[16][128];
    __shared__ float Bs[16][48];
    int tid = threadIdx.x;
    int tx = tid & 15, ty = tid >> 4;
    int m0 = blockIdx.y * 128;
    int s  = blockIdx.z >> 3;
    int kz = blockIdx.z & 7;
    const float* A  = g_xa[s];
    const float* Bm = P.br[s].xpw;
    float*       C  = g_dbc[s];

    int srow = tid >> 1;
    int skq  = (tid & 1) * 8;
    bool mok = (m0 + srow) < BLT;
    const float* Ap = A + (size_t)(m0 + srow) * EDI + kz * DBC_KL + skq;
    int brow = tid >> 2, bkq = (tid & 3) * 4;
    bool bok = tid < 192;
    const float* Bp = Bm + (size_t)brow * EDI + kz * DBC_KL + bkq;

    float4 a0 = make_float4(0,0,0,0), a1 = a0, b0 = a0;
    if (mok) { a0 = *(const float4*)Ap; a1 = *(const float4*)(Ap + 4); }
    if (bok) b0 = *(const float4*)Bp;
    Ap += 16; Bp += 16;

    float acc[8][3];
#pragma unroll
    for (int i = 0; i < 8; i++)
#pragma unroll
        for (int j = 0; j < 3; j++) acc[i][j] = 0.f;

    for (int c = 0; c < DBC_KL / 16; c++) {
        As[skq+0][srow]=a0.x; As[skq+1][srow]=a0.y; As[skq+2][srow]=a0.z; As[skq+3][srow]=a0.w;
        As[skq+4][srow]=a1.x; As[skq+5][srow]=a1.y; As[skq+6][srow]=a1.z; As[skq+7][srow]=a1.w;
        if (bok) {
            Bs[bkq+0][brow]=b0.x; Bs[bkq+1][brow]=b0.y;
            Bs[bkq+2][brow]=b0.z; Bs[bkq+3][brow]=b0.w;
        }
        __syncthreads();
        if (c + 1 < DBC_KL / 16) {
            a0 = make_float4(0,0,0,0); a1 = a0; b0 = a0;
            if (mok) { a0 = *(const float4*)Ap; a1 = *(const float4*)(Ap + 4); }
            if (bok) b0 = *(const float4*)Bp;
            Ap += 16; Bp += 16;
        }
#pragma unroll
        for (int k = 0; k < 16; k++) {
            float4 av0 = *(float4*)&As[k][ty*4];
            float4 av1 = *(float4*)&As[k][64 + ty*4];
            float a4[8] = {av0.x,av0.y,av0.z,av0.w, av1.x,av1.y,av1.z,av1.w};
            float b4[3] = {Bs[k][tx*3], Bs[k][tx*3+1], Bs[k][tx*3+2]};
#pragma unroll
            for (int i = 0; i < 8; i++)
#pragma unroll
                for (int j = 0; j < 3; j++)
                    acc[i][j] = fmaf(a4[i], b4[j], acc[i][j]);
        }
        __syncthreads();
    }
#pragma unroll
    for (int i = 0; i < 8; i++) {
        int m = m0 + (i >> 2) * 64 + ty * 4 + (i & 3);
        if (m >= BLT) continue;
#pragma unroll
        for (int j = 0; j < 3; j++)
            atomicAdd(&C[(size_t)m * DBCW + tx * 3 + j], acc[i][j]);
    }
}

// ===== out-GEMM fused with branch combine (permutation gather), splitK(8) ===
#define OUT_KS 8
#define OUT_KL (EDI / OUT_KS)   // 64
__global__ __launch_bounds__(256)
void out_gemm_fused(const float* __restrict__ out_w, float* __restrict__ C) {
    __shared__ float As[16][128];
    __shared__ float Bs[16][128];
    int tid = threadIdx.x;
    int tx = tid & 15, ty = tid >> 4;
    int m0 = blockIdx.y * 128, n0 = blockIdx.x * 128;
    int kz = blockIdx.z;
    int srow = tid >> 1;
    int skq  = (tid & 1) * 8;
    int m = m0 + srow;
    bool mok = m < BLT;
    size_t r0 = 0, r1 = 0, r2 = 0, r3 = 0;
    if (mok) {
        int b = m / LSEQ, l = m % LSEQ;
        r0 = (size_t)m * EDI;
        r1 = (size_t)(b * LSEQ + (LSEQ - 1 - l)) * EDI;
        r2 = (size_t)(b * LSEQ + pi_map(l)) * EDI;
        r3 = (size_t)(b * LSEQ + pi_map(LSEQ - 1 - l)) * EDI;
    }
    const float* Bp = out_w + (size_t)(n0 + srow) * EDI + kz * OUT_KL + skq;

    float4 a0, a1, b0, b1;
    int kk = kz * OUT_KL + skq;
    a0 = make_float4(0,0,0,0); a1 = a0;
    if (mok) {
        float4 p0 = *(const float4*)(g_g[0]+r0+kk), p1 = *(const float4*)(g_g[1]+r1+kk);
        float4 p2 = *(const float4*)(g_g[2]+r2+kk), p3 = *(const float4*)(g_g[3]+r3+kk);
        a0.x = 0.25f*(p0.x+p1.x+p2.x+p3.x); a0.y = 0.25f*(p0.y+p1.y+p2.y+p3.y);
        a0.z = 0.25f*(p0.z+p1.z+p2.z+p3.z); a0.w = 0.25f*(p0.w+p1.w+p2.w+p3.w);
        float4 q0 = *(const float4*)(g_g[0]+r0+kk+4), q1 = *(const float4*)(g_g[1]+r1+kk+4);
        float4 q2 = *(const float4*)(g_g[2]+r2+kk+4), q3 = *(const float4*)(g_g[3]+r3+kk+4);
        a1.x = 0.25f*(q0.x+q1.x+q2.x+q3.x); a1.y = 0.25f*(q0.y+q1.y+q2.y+q3.y);
        a1.z = 0.25f*(q0.z+q1.z+q2.z+q3.z); a1.w = 0.25f*(q0.w+q1.w+q2.w+q3.w);
    }
    b0 = *(const float4*)Bp; b1 = *(const float4*)(Bp + 4);
    Bp += 16;

    float acc[8][8];
#pragma unroll
    for (int i = 0; i < 8; i++)
#pragma unroll
        for (int j = 0; j < 8; j++) acc[i][j] = 0.f;

    for (int c = 0; c < OUT_KL / 16; c++) {
        As[skq+0][srow]=a0.x; As[skq+1][srow]=a0.y; As[skq+2][srow]=a0.z; As[skq+3][srow]=a0.w;
        As[skq+4][srow]=a1.x; As[skq+5][srow]=a1.y; As[skq+6][srow]=a1.z; As[skq+7][srow]=a1.w;
        Bs[skq+0][srow]=b0.x; Bs[skq+1][srow]=b0.y; Bs[skq+2][srow]=b0.z; Bs[skq+3][srow]=b0.w;
        Bs[skq+4][srow]=b1.x; Bs[skq+5][srow]=b1.y; Bs[skq+6][srow]=b1.z; Bs[skq+7][srow]=b1.w;
        __syncthreads();
        if (c + 1 < OUT_KL / 16) {
            kk = kz * OUT_KL + (c + 1) * 16 + skq;
            a0 = make_float4(0,0,0,0); a1 = a0;
            if (mok) {
                float4 p0 = *(const float4*)(g_g[0]+r0+kk), p1 = *(const float4*)(g_g[1]+r1+kk);
                float4 p2 = *(const float4*)(g_g[2]+r2+kk), p3 = *(const float4*)(g_g[3]+r3+kk);
                a0.x = 0.25f*(p0.x+p1.x+p2.x+p3.x); a0.y = 0.25f*(p0.y+p1.y+p2.y+p3.y);
                a0.z = 0.25f*(p0.z+p1.z+p2.z+p3.z); a0.w = 0.25f*(p0.w+p1.w+p2.w+p3.w);
                float4 q0 = *(const float4*)(g_g[0]+r0+kk+4), q1 = *(const float4*)(g_g[1]+r1+kk+4);
                float4 q2 = *(const float4*)(g_g[2]+r2+kk+4), q3 = *(const float4*)(g_g[3]+r3+kk+4);
                a1.x = 0.25f*(q0.x+q1.x+q2.x+q3.x); a1.y = 0.25f*(q0.y+q1.y+q2.y+q3.y);
                a1.z = 0.25f*(q0.z+q1.z+q2.z+q3.z); a1.w = 0.25f*(q0.w+q1.w+q2.w+q3.w);
            }
            b0 = *(const float4*)Bp; b1 = *(const float4*)(Bp + 4);
            Bp += 16;
        }
#pragma unroll
        for (int k = 0; k < 16; k++) {
            float4 av0 = *(float4*)&As[k][ty*4];
            float4 av1 = *(float4*)&As[k][64 + ty*4];
            float4 bv0 = *(float4*)&Bs[k][tx*4];
            float4 bv1 = *(float4*)&Bs[k][64 + tx*4];
            float a4[8] = {av0.x,av0.y,av0.z,av0.w, av1.x,av1.y,av1.z,av1.w};
            float b4[8] = {bv0.x,bv0.y,bv0.z,bv0.w, bv1.x,bv1.y,bv1.z,bv1.w};
#pragma unroll
            for (int i = 0; i < 8; i++)
#pragma unroll
                for (int j = 0; j < 8; j++)
                    acc[i][j] = fmaf(a4[i], b4[j], acc[i][j]);
        }
        __syncthreads();
    }
#pragma unroll
    for (int i = 0; i < 8; i++) {
        int mm = m0 + (i >> 2) * 64 + ty * 4 + (i & 3);
        if (mm >= BLT) continue;
#pragma unroll
        for (int j = 0; j < 8; j++) {
            int n = n0 + (j >> 2) * 64 + tx * 4 + (j & 3);
            atomicAdd(&C[(size_t)mm * DMO + n], acc[i][j]);
        }
    }
}

// ------------------------- structure check for A = -(n+1) -------------------
__global__ void flag_kernel(AllPtrs P) {
    __shared__ int ok;
    int s = blockIdx.x;
    if (threadIdx.x == 0) ok = 1;
    __syncthreads();
    const float* Al = P.br[s].Al;
    int e = threadIdx.x;
    bool good = true;
#pragma unroll
    for (int n = 0; n < NS; n++) {
        float ref = logf((float)(n + 1));
        if (fabsf(Al[e * NS + n] - ref) > 1e-5f * fmaxf(1.f, fabsf(ref))) good = false;
    }
    if (!good) atomicAnd(&ok, 0);
    __syncthreads();
    if (threadIdx.x == 0) g_fast[s] = ok;
}

// ------- depthwise conv (K=4 causal) + SiLU, rolling window over 6 pos ------
#define CONV_T 6
__global__ __launch_bounds__(512)
void conv_silu(AllPtrs P) {
    int blk = blockIdx.x;
    int ntile = LSEQ / CONV_T;           // 171
    int s  = blk / (BB * ntile);
    int rm = blk % (BB * ntile);
    int b  = rm / ntile;
    int l0 = (rm % ntile) * CONV_T;
    int e  = threadIdx.x;
    float4 cwv = *(const float4*)(P.br[s].cw + e * 4);
    float cb = P.br[s].cb[e];
    float v0 = 0.f, v1 = 0.f, v2 = 0.f;
    if (l0 - 3 >= 0) v0 = g_xz[(size_t)(b * LSEQ + in_row(s, l0 - 3)) * ED2 + e];
    if (l0 - 2 >= 0) v1 = g_xz[(size_t)(b * LSEQ + in_row(s, l0 - 2)) * ED2 + e];
    if (l0 - 1 >= 0) v2 = g_xz[(size_t)(b * LSEQ + in_row(s, l0 - 1)) * ED2 + e];
#pragma unroll
    for (int t = 0; t < CONV_T; t++) {
        int l = l0 + t;
        float v3 = g_xz[(size_t)(b * LSEQ + in_row(s, l)) * ED2 + e];
        float acc = cb;
        acc = fmaf(cwv.x, v0, acc);
        acc = fmaf(cwv.y, v1, acc);
        acc = fmaf(cwv.z, v2, acc);
        acc = fmaf(cwv.w, v3, acc);
        float sg = 1.f / (1.f + __expf(-acc));
        g_xa[s][(size_t)(b * LSEQ + l) * EDI + e] = acc * sg;
        v0 = v1; v1 = v2; v2 = v3;
    }
}

// -------- scan phase 1: chunk summaries, delta fused, channel-split ---------
__global__ __launch_bounds__(256)
void scan1(AllPtrs P) {
    __shared__ float dtw_s[EHALF * 17];
    __shared__ float f_s[CLEN][NS];
    __shared__ float Bsm[CLEN * NS];
    int blk = blockIdx.x;
    int half = blk & 1;
    int blk2 = blk >> 1;
    int s = blk2 / (BB * NCHK);
    int rem = blk2 % (BB * NCHK);
    int b = rem / NCHK, c = rem % NCHK;
    int e0 = half * EHALF;
    int e = e0 + threadIdx.x;
    const float* dtw = P.br[s].dtw;
    for (int idx = threadIdx.x; idx < EHALF * RRW; idx += blockDim.x)
        dtw_s[(idx >> 4) * 17 + (idx & 15)] = dtw[e0 * RRW + idx];
    for (int idx = threadIdx.x; idx < CLEN * 32; idx += blockDim.x) {
        int t = idx >> 5, q = idx & 31;
        float v = g_dbc[s][(size_t)(b * LSEQ + c * CLEN + t) * DBCW + q];
        if (q < 16) f_s[t][q] = v;
        else        Bsm[t * NS + (q - 16)] = v;
    }
    __syncthreads();
    float w[RRW];
#pragma unroll
    for (int q = 0; q < RRW; q++) w[q] = dtw_s[threadIdx.x * 17 + q];
    float dtb = P.br[s].dtb[e];
    int fast = g_fast[s];
    float A_[NS];
    if (!fast) {
        const float* Al = P.br[s].Al;
#pragma unroll
        for (int n = 0; n < NS; n++) A_[n] = -__expf(Al[e * NS + n]);
    }
    float h[NS], Pn[NS];
#pragma unroll
    for (int n = 0; n < NS; n++) { h[n] = 0.f; Pn[n] = 1.f; }
    float Rp = 1.f;
    const float* xptr = g_xa[s] + (size_t)(b * LSEQ + c * CLEN) * EDI + e;
    for (int t = 0; t < CLEN; t++) {
        float u = dtb;
#pragma unroll
        for (int q = 0; q < RRW; q++) u = fmaf(f_s[t][q], w[q], u);
        float d = fmaxf(u, 0.f) + log1pf(__expf(-fabsf(u)));
        float x = xptr[(size_t)t * EDI];
        float dx = d * x;
        if (fast) {
            float r = __expf(-d);
            Rp *= r;
            float dA = 1.f;
#pragma unroll
            for (int n = 0; n < NS; n++) {
                dA *= r;
                h[n] = fmaf(dA, h[n], dx * Bsm[t * NS + n]);
            }
        } else {
#pragma unroll
            for (int n = 0; n < NS; n++) {
                float dA = __expf(d * A_[n]);
                Pn[n] *= dA;
                h[n] = fmaf(dA, h[n], dx * Bsm[t * NS + n]);
            }
        }
    }
    if (fast) {
        float q = 1.f;
#pragma unroll
        for (int n = 0; n < NS; n++) { q *= Rp; Pn[n] = q; }
    }
    size_t base = (size_t)((s * BB + b) * NCHK + c) * 32 * EDI + e;
#pragma unroll
    for (int n = 0; n < NS; n++) g_sum[base + (size_t)n * EDI] = h[n];
#pragma unroll
    for (int n = 0; n < NS; n++) g_sum[base + (size_t)(16 + n) * EDI] = Pn[n];
}

// ---------- scan phase 2: chunk combine, parallel over (s,b,n) --------------
__global__ __launch_bounds__(512)
void scan2() {
    int n = blockIdx.x & 15;
    int sb = blockIdx.x >> 4;          // s*BB+b
    int e = threadIdx.x;
    float h = 0.f;
    for (int c = 0; c < NCHK; c++) {
        size_t idx = (size_t)(sb * NCHK + c);
        g_h0[idx * NS * EDI + (size_t)n * EDI + e] = h;
        size_t pb = idx * 32 * EDI + e;
        float hl = g_sum[pb + (size_t)n * EDI];
        float Pv = g_sum[pb + (size_t)(16 + n) * EDI];
        h = fmaf(Pv, h, hl);
    }
}

// -------- scan phase 3: full walk + gate, delta fused, channel-split --------
__global__ __launch_bounds__(256)
void scan3(AllPtrs P) {
    __shared__ float dtw_s[EHALF * 17];
    __shared__ float f_s[CLEN][NS];
    __shared__ float Bsm[CLEN * NS];
    __shared__ float Csm[CLEN * NS];
    int blk = blockIdx.x;
    int half = blk & 1;
    int blk2 = blk >> 1;
    int s = blk2 / (BB * NCHK);
    int rem = blk2 % (BB * NCHK);
    int b = rem / NCHK, c = rem % NCHK;
    int e0 = half * EHALF;
    int e = e0 + threadIdx.x;
    const float* dtw = P.br[s].dtw;
    for (int idx = threadIdx.x; idx < EHALF * RRW; idx += blockDim.x)
        dtw_s[(idx >> 4) * 17 + (idx & 15)] = dtw[e0 * RRW + idx];
    for (int idx = threadIdx.x; idx < CLEN * DBCW; idx += blockDim.x) {
        int t = idx / DBCW, q = idx % DBCW;
        float v = g_dbc[s][(size_t)(b * LSEQ + c * CLEN + t) * DBCW + q];
        if (q < 16)      f_s[t][q] = v;
        else if (q < 32) Bsm[t * NS + (q - 16)] = v;
        else             Csm[t * NS + (q - 32)] = v;
    }
    __syncthreads();
    float w[RRW];
#pragma unroll
    for (int q = 0; q < RRW; q++) w[q] = dtw_s[threadIdx.x * 17 + q];
    float dtb = P.br[s].dtb[e];
    int fast = g_fast[s];
    float A_[NS];
    if (!fast) {
        const float* Al = P.br[s].Al;
#pragma unroll
        for (int n = 0; n < NS; n++) A_[n] = -__expf(Al[e * NS + n]);
    }
    float Dv = P.br[s].Dp[e];
    float h[NS];
    {
        size_t sb = (size_t)((s * BB + b) * NCHK + c);
        size_t hb = sb * NS * EDI + e;
#pragma unroll
        for (int n = 0; n < NS; n++) h[n] = g_h0[hb + (size_t)n * EDI];
    }
    for (int t = 0; t < CLEN; t++) {
        int l = c * CLEN + t;
        int bl = b * LSEQ + l;
        float u = dtb;
#pragma unroll
        for (int q = 0; q < RRW; q++) u = fmaf(f_s[t][q], w[q], u);
        float d = fmaxf(u, 0.f) + log1pf(__expf(-fabsf(u)));
        float x = g_xa[s][(size_t)bl * EDI + e];
        float dx = d * x;
        float acc = Dv * x;
        if (fast) {
            float r = __expf(-d);
            float dA = 1.f;
#pragma unroll
            for (int n = 0; n < NS; n++) {
                dA *= r;
                h[n] = fmaf(dA, h[n], dx * Bsm[t * NS + n]);
                acc = fmaf(h[n], Csm[t * NS + n], acc);
            }
        } else {
#pragma unroll
            for (int n = 0; n < NS; n++) {
                float dA = __expf(d * A_[n]);
                h[n] = fmaf(dA, h[n], dx * Bsm[t * NS + n]);
                acc = fmaf(h[n], Csm[t * NS + n], acc);
            }
        }
        int zr = b * LSEQ + in_row(s, l);
        float za = g_xz[(size_t)zr * ED2 + EDI + e];
        float sz = za / (1.f + __expf(-za));
        g_g[s][(size_t)bl * EDI + e] = acc * sz;
    }
}

// ------------------------- launch ------------------------------------------
extern "C" void kernel_launch(void* const* d_in, const int* in_sizes, int n_in,
                              void* d_out, int out_size) {
    const float* x     = (const float*)d_in[0];
    const float* in_w  = (const float*)d_in[1];
    const float* out_w = (const float*)d_in[2];
    AllPtrs P;
    for (int s = 0; s < NBR; s++) {
        int o = 3 + 7 * s;
        P.br[s].cw  = (const float*)d_in[o + 0];
        P.br[s].cb  = (const float*)d_in[o + 1];
        P.br[s].xpw = (const float*)d_in[o + 2];
        P.br[s].dtw = (const float*)d_in[o + 3];
        P.br[s].dtb = (const float*)d_in[o + 4];
        P.br[s].Al  = (const float*)d_in[o + 5];
        P.br[s].Dp  = (const float*)d_in[o + 6];
    }
    float *p_xz, *p_dbc;
    cudaGetSymbolAddress((void**)&p_xz,  g_xz);
    cudaGetSymbolAddress((void**)&p_dbc, g_dbc);

    flag_kernel<<<NBR, EDI>>>(P);

    // xz = x @ in_w^T : [2052,1024], K=256 — 272 blocks
    sgemm_nt_12864<<<dim3(ED2 / 64, (BLT + 127) / 128), 256>>>(x, in_w, p_xz, BLT, ED2, DMO);

    // per-branch permuted depthwise conv + SiLU — 1368 blocks
    conv_silu<<<NBR * BB * (LSEQ / CONV_T), 512>>>(P);

    // dBC: batched split-K(8) — 544 blocks
    cudaMemsetAsync(p_dbc, 0, (size_t)NBR * BLT * DBCW * sizeof(float));
    dbc_gemm<<<dim3(1, (BLT + 127) / 128, NBR * DBC_KS), 256>>>(P);

    // chunked selective scan (delta fused) — 288 / 128 / 288 blocks
    scan1<<<NBR * BB * NCHK * 2, 256>>>(P);
    scan2<<<NBR * BB * NS, EDI>>>();
    scan3<<<NBR * BB * NCHK * 2, 256>>>(P);

    // fused combine + out-proj — 272 blocks
    cudaMemsetAsync(d_out, 0, (size_t)BLT * DMO * sizeof(float));
    out_gemm_fused<<<dim3(DMO / 128, (BLT + 127) / 128, OUT_KS), 256>>>(out_w, (float*)d_out);
}